// round 1
// baseline (speedup 1.0000x reference)
#include <cuda_runtime.h>
#include <cuda_bf16.h>
#include <math.h>

// Problem constants
#define BB 2
#define TT 2048
#define CC 2048
#define HH 16
#define HKV 8
#define DD 128
#define NROW (BB*TT)          // 4096

// ---------------- scratch (device globals; no allocation allowed) ----------
__device__ float g_q[(size_t)NROW * CC];        // 32 MB
__device__ float g_k[(size_t)NROW * (HKV*DD)];  // 16 MB
__device__ float g_v[(size_t)NROW * (HKV*DD)];  // 16 MB
__device__ float g_o[(size_t)NROW * CC];        // 32 MB

// ---------------- SGEMM: C[M,N] = A[M,K] @ B[K,N]  (all row-major fp32) ----
#define GBM 128
#define GBN 128
#define GBK 8

__global__ void __launch_bounds__(256) sgemm_kernel(
    const float* __restrict__ A, const float* __restrict__ B,
    float* __restrict__ C, int M, int N, int K)
{
    __shared__ float As[GBK][GBM + 4];   // transposed, padded
    __shared__ float Bs[GBK][GBN];

    const int tid = threadIdx.x;
    const int cRow = blockIdx.y, cCol = blockIdx.x;

    const float* Ab = A + (size_t)cRow * GBM * K;
    const float* Bb = B + (size_t)cCol * GBN;
    float*       Cb = C + (size_t)cRow * GBM * N + (size_t)cCol * GBN;

    const int tr = tid >> 4;          // 0..15
    const int tc = tid & 15;          // 0..15

    const int aRow = tid >> 1;        // 0..127
    const int aCol = (tid & 1) * 4;   // 0 or 4
    const int bRow = tid >> 5;        // 0..7
    const int bCol = (tid & 31) * 4;  // 0..124

    float acc[8][8];
    #pragma unroll
    for (int i = 0; i < 8; i++)
        #pragma unroll
        for (int j = 0; j < 8; j++) acc[i][j] = 0.f;

    for (int k0 = 0; k0 < K; k0 += GBK) {
        float4 at = *(const float4*)(Ab + (size_t)aRow * K + k0 + aCol);
        As[aCol + 0][aRow] = at.x;
        As[aCol + 1][aRow] = at.y;
        As[aCol + 2][aRow] = at.z;
        As[aCol + 3][aRow] = at.w;
        *(float4*)(&Bs[bRow][bCol]) =
            *(const float4*)(Bb + (size_t)(k0 + bRow) * N + bCol);
        __syncthreads();

        #pragma unroll
        for (int kk = 0; kk < GBK; kk++) {
            float ra[8], rb[8];
            *(float4*)(ra)     = *(const float4*)(&As[kk][tr * 8]);
            *(float4*)(ra + 4) = *(const float4*)(&As[kk][tr * 8 + 4]);
            *(float4*)(rb)     = *(const float4*)(&Bs[kk][tc * 8]);
            *(float4*)(rb + 4) = *(const float4*)(&Bs[kk][tc * 8 + 4]);
            #pragma unroll
            for (int i = 0; i < 8; i++)
                #pragma unroll
                for (int j = 0; j < 8; j++)
                    acc[i][j] += ra[i] * rb[j];
        }
        __syncthreads();
    }

    #pragma unroll
    for (int i = 0; i < 8; i++) {
        float* crow = Cb + (size_t)(tr * 8 + i) * N + tc * 8;
        *(float4*)(crow)     = make_float4(acc[i][0], acc[i][1], acc[i][2], acc[i][3]);
        *(float4*)(crow + 4) = make_float4(acc[i][4], acc[i][5], acc[i][6], acc[i][7]);
    }
}

// ---------------- RoPE (in-place) ------------------------------------------
__global__ void rope_kernel(float* __restrict__ buf, int n_heads, int total)
{
    int idx = blockIdx.x * blockDim.x + threadIdx.x;
    if (idx >= total) return;
    int j = idx & 63;
    int h = (idx >> 6) % n_heads;
    int r = idx / (64 * n_heads);
    int t = r & (TT - 1);

    float e = (float)(2 * j) * (1.0f / 128.0f);
    float inv = 1.0f / powf(10000.0f, e);
    float f = (float)t * inv;
    float c = cosf(f), s = sinf(f);

    float* p = buf + (size_t)r * (n_heads * DD) + h * DD;
    float x1 = p[j], x2 = p[j + 64];
    p[j]      = x1 * c - x2 * s;
    p[j + 64] = x2 * c + x1 * s;
}

// ---------------- Flash attention (causal, GQA) -----------------------------
// grid: (T/BQ, H, B), block 256.  thread tid = qloc*8 + g  (qloc 0..31, g 0..7)
#define BQ 32
#define BK 64
#define QS_STRIDE 132          // floats (padded)
#define KS_STRIDE 132
#define QS_OFF 0
#define KS_OFF (BQ * QS_STRIDE)                    // 4224
#define VS_OFF (KS_OFF + BK * KS_STRIDE)           // 12672
#define P_OFF  (VS_OFF + BK * DD)                  // 20864
#define SMEM_FLOATS (P_OFF + BQ * BK)              // 22912
#define SMEM_BYTES (SMEM_FLOATS * 4)               // 91648
#define ATTN_SCALE 0.08838834764831843f            // 1/sqrt(128)

__global__ void __launch_bounds__(256) attn_kernel(
    const float* __restrict__ Q, const float* __restrict__ K,
    const float* __restrict__ V, float* __restrict__ O)
{
    extern __shared__ float sm[];
    float4* Qs4 = (float4*)(sm + QS_OFF);
    float4* Ks4 = (float4*)(sm + KS_OFF);
    float4* Vs4 = (float4*)(sm + VS_OFF);
    float*  Psm = sm + P_OFF;

    const int tid  = threadIdx.x;
    const int qloc = tid >> 3;
    const int g    = tid & 7;
    const int qi   = (gridDim.x - 1 - blockIdx.x);   // big tiles first
    const int h    = blockIdx.y;
    const int b    = blockIdx.z;
    const int hk   = h >> 1;                          // GQA group of 2

    // load Q tile (32 x 128) into padded smem
    #pragma unroll
    for (int i = 0; i < 4; i++) {
        int lin = tid + 256 * i;       // 0..1023 float4 tasks
        int row = lin >> 5;            // 0..31
        int c4  = lin & 31;
        float4 qv = *(const float4*)(Q + ((size_t)(b * TT + qi * BQ + row) * HH + h) * DD + c4 * 4);
        Qs4[row * (QS_STRIDE / 4) + c4] = qv;
    }

    const int q_global = qi * BQ + qloc;
    float m = -INFINITY;
    float l = 0.f;
    float4 acc0 = {0,0,0,0}, acc1 = {0,0,0,0}, acc2 = {0,0,0,0}, acc3 = {0,0,0,0};

    const int ntiles = (qi * BQ + BQ - 1) / BK + 1;

    for (int t0 = 0; t0 < ntiles; t0++) {
        const int k0 = t0 * BK;
        __syncthreads();   // prev PV done reading Vs/P before overwrite

        // load K,V tiles (64 x 128 each)
        #pragma unroll
        for (int i = 0; i < 8; i++) {
            int lin = tid + 256 * i;   // 0..2047
            int row = lin >> 5;        // 0..63
            int c4  = lin & 31;
            size_t gidx = ((size_t)(b * TT + k0 + row) * HKV + hk) * DD + c4 * 4;
            Ks4[row * (KS_STRIDE / 4) + c4] = *(const float4*)(K + gidx);
            Vs4[row * (DD / 4) + c4]        = *(const float4*)(V + gidx);
        }
        __syncthreads();

        // scores: this thread owns k = g + 8j, j = 0..7
        float s8[8];
        #pragma unroll
        for (int j = 0; j < 8; j++) s8[j] = 0.f;

        #pragma unroll 4
        for (int d4 = 0; d4 < 32; d4++) {
            float4 qv = Qs4[qloc * (QS_STRIDE / 4) + d4];
            #pragma unroll
            for (int j = 0; j < 8; j++) {
                float4 kv = Ks4[(g + 8 * j) * (KS_STRIDE / 4) + d4];
                s8[j] += qv.x * kv.x + qv.y * kv.y + qv.z * kv.z + qv.w * kv.w;
            }
        }

        // scale + causal mask
        float mx = -INFINITY;
        #pragma unroll
        for (int j = 0; j < 8; j++) {
            int kg = k0 + g + 8 * j;
            float sv = s8[j] * ATTN_SCALE;
            if (kg > q_global) sv = -INFINITY;
            s8[j] = sv;
            mx = fmaxf(mx, sv);
        }
        // reduce max over the 8 lanes of this query row
        #pragma unroll
        for (int off = 1; off < 8; off <<= 1)
            mx = fmaxf(mx, __shfl_xor_sync(0xffffffffu, mx, off));

        float m_new = fmaxf(m, mx);
        float alpha = expf(m - m_new);          // 0 on first tile (m=-inf)

        float lsum = 0.f;
        #pragma unroll
        for (int j = 0; j < 8; j++) {
            float p = expf(s8[j] - m_new);      // -inf -> 0
            lsum += p;
            Psm[qloc * BK + g + 8 * j] = p;
        }
        #pragma unroll
        for (int off = 1; off < 8; off <<= 1)
            lsum += __shfl_xor_sync(0xffffffffu, lsum, off);

        l = l * alpha + lsum;
        m = m_new;
        acc0.x *= alpha; acc0.y *= alpha; acc0.z *= alpha; acc0.w *= alpha;
        acc1.x *= alpha; acc1.y *= alpha; acc1.z *= alpha; acc1.w *= alpha;
        acc2.x *= alpha; acc2.y *= alpha; acc2.z *= alpha; acc2.w *= alpha;
        acc3.x *= alpha; acc3.y *= alpha; acc3.z *= alpha; acc3.w *= alpha;

        __syncwarp();   // P written/read within the same warp

        // PV: thread owns output dims {g*4 + 32*i + 0..3}
        #pragma unroll 4
        for (int k = 0; k < BK; k++) {
            float p = Psm[qloc * BK + k];
            float4 v0 = Vs4[k * 32 + g];
            float4 v1 = Vs4[k * 32 + g + 8];
            float4 v2 = Vs4[k * 32 + g + 16];
            float4 v3 = Vs4[k * 32 + g + 24];
            acc0.x += p * v0.x; acc0.y += p * v0.y; acc0.z += p * v0.z; acc0.w += p * v0.w;
            acc1.x += p * v1.x; acc1.y += p * v1.y; acc1.z += p * v1.z; acc1.w += p * v1.w;
            acc2.x += p * v2.x; acc2.y += p * v2.y; acc2.z += p * v2.z; acc2.w += p * v2.w;
            acc3.x += p * v3.x; acc3.y += p * v3.y; acc3.z += p * v3.z; acc3.w += p * v3.w;
        }
    }

    float invl = 1.0f / l;
    float* orow = O + ((size_t)(b * TT) + q_global) * CC + h * DD;
    float4 w;
    w = make_float4(acc0.x*invl, acc0.y*invl, acc0.z*invl, acc0.w*invl); *(float4*)(orow + g*4)      = w;
    w = make_float4(acc1.x*invl, acc1.y*invl, acc1.z*invl, acc1.w*invl); *(float4*)(orow + g*4 + 32) = w;
    w = make_float4(acc2.x*invl, acc2.y*invl, acc2.z*invl, acc2.w*invl); *(float4*)(orow + g*4 + 64) = w;
    w = make_float4(acc3.x*invl, acc3.y*invl, acc3.z*invl, acc3.w*invl); *(float4*)(orow + g*4 + 96) = w;
}

// ---------------- host entry -------------------------------------------------
extern "C" void kernel_launch(void* const* d_in, const int* in_sizes, int n_in,
                              void* d_out, int out_size)
{
    const float* x  = (const float*)d_in[0];
    const float* Wq = (const float*)d_in[1];
    const float* Wk = (const float*)d_in[2];
    const float* Wv = (const float*)d_in[3];
    const float* Wp = (const float*)d_in[4];
    float* out = (float*)d_out;

    float *q, *k, *v, *o;
    cudaGetSymbolAddress((void**)&q, g_q);
    cudaGetSymbolAddress((void**)&k, g_k);
    cudaGetSymbolAddress((void**)&v, g_v);
    cudaGetSymbolAddress((void**)&o, g_o);

    // projections
    sgemm_kernel<<<dim3(CC / GBN, NROW / GBM), 256>>>(x, Wq, q, NROW, CC, CC);
    sgemm_kernel<<<dim3((HKV*DD) / GBN, NROW / GBM), 256>>>(x, Wk, k, NROW, HKV*DD, CC);
    sgemm_kernel<<<dim3((HKV*DD) / GBN, NROW / GBM), 256>>>(x, Wv, v, NROW, HKV*DD, CC);

    // RoPE
    {
        int totq = NROW * HH * 64;
        rope_kernel<<<(totq + 255) / 256, 256>>>(q, HH, totq);
        int totk = NROW * HKV * 64;
        rope_kernel<<<(totk + 255) / 256, 256>>>(k, HKV, totk);
    }

    // attention
    cudaFuncSetAttribute(attn_kernel, cudaFuncAttributeMaxDynamicSharedMemorySize, SMEM_BYTES);
    attn_kernel<<<dim3(TT / BQ, HH, BB), 256, SMEM_BYTES>>>(q, k, v, o);

    // output projection
    sgemm_kernel<<<dim3(CC / GBN, NROW / GBM), 256>>>(o, Wp, out, NROW, CC, CC);
}

// round 3
// speedup vs baseline: 1.4670x; 1.4670x over previous
#include <cuda_runtime.h>
#include <cuda_bf16.h>
#include <math.h>
#include <cstdint>

// Problem constants
#define BB 2
#define TT 2048
#define CC 2048
#define HH 16
#define HKV 8
#define DD 128
#define NROW (BB*TT)          // 4096

// ---------------- scratch (device globals; no allocation allowed) ----------
__device__ float g_q[(size_t)NROW * CC];
__device__ float g_k[(size_t)NROW * (HKV*DD)];
__device__ float g_v[(size_t)NROW * (HKV*DD)];
__device__ float g_o[(size_t)NROW * CC];

__device__ __align__(16) __nv_bfloat16 g_xhi[(size_t)NROW * CC];
__device__ __align__(16) __nv_bfloat16 g_xlo[(size_t)NROW * CC];
__device__ __align__(16) __nv_bfloat16 g_ohi[(size_t)NROW * CC];
__device__ __align__(16) __nv_bfloat16 g_olo[(size_t)NROW * CC];
__device__ __align__(16) __nv_bfloat16 g_wqh[(size_t)CC * CC];
__device__ __align__(16) __nv_bfloat16 g_wql[(size_t)CC * CC];
__device__ __align__(16) __nv_bfloat16 g_wph[(size_t)CC * CC];
__device__ __align__(16) __nv_bfloat16 g_wpl[(size_t)CC * CC];
__device__ __align__(16) __nv_bfloat16 g_wkh[(size_t)(HKV*DD) * CC];
__device__ __align__(16) __nv_bfloat16 g_wkl[(size_t)(HKV*DD) * CC];
__device__ __align__(16) __nv_bfloat16 g_wvh[(size_t)(HKV*DD) * CC];
__device__ __align__(16) __nv_bfloat16 g_wvl[(size_t)(HKV*DD) * CC];

// ======================= low-level helpers ==================================
__device__ __forceinline__ uint32_t smem_u32(const void* p) {
    uint32_t a;
    asm("{ .reg .u64 t; cvta.to.shared.u64 t, %1; cvt.u32.u64 %0, t; }"
        : "=r"(a) : "l"(p));
    return a;
}
__device__ __forceinline__ void ldsm4(uint32_t* r, uint32_t addr) {
    asm volatile("ldmatrix.sync.aligned.m8n8.x4.shared.b16 {%0,%1,%2,%3}, [%4];"
        : "=r"(r[0]), "=r"(r[1]), "=r"(r[2]), "=r"(r[3]) : "r"(addr));
}
__device__ __forceinline__ void mma_bf16(float* d, const uint32_t* a, const uint32_t* b) {
    asm volatile(
        "mma.sync.aligned.m16n8k16.row.col.f32.bf16.bf16.f32 "
        "{%0,%1,%2,%3}, {%4,%5,%6,%7}, {%8,%9}, {%0,%1,%2,%3};"
        : "+f"(d[0]), "+f"(d[1]), "+f"(d[2]), "+f"(d[3])
        : "r"(a[0]), "r"(a[1]), "r"(a[2]), "r"(a[3]), "r"(b[0]), "r"(b[1]));
}
__device__ __forceinline__ void cp_async16(uint32_t dst, const void* src) {
    asm volatile("cp.async.cg.shared.global [%0], [%1], 16;\n" :: "r"(dst), "l"(src));
}
#define CP_COMMIT() asm volatile("cp.async.commit_group;\n" ::: "memory")
#define CP_WAIT1()  asm volatile("cp.async.wait_group 1;\n" ::: "memory")
#define CP_WAIT0()  asm volatile("cp.async.wait_group 0;\n" ::: "memory")

// ======================= conversion kernels =================================
__global__ void split_kernel(const float4* __restrict__ in,
                             __nv_bfloat162* __restrict__ hi,
                             __nv_bfloat162* __restrict__ lo, int n4)
{
    int i = blockIdx.x * blockDim.x + threadIdx.x;
    if (i >= n4) return;
    float4 v = in[i];
    __nv_bfloat16 h0 = __float2bfloat16(v.x);
    __nv_bfloat16 h1 = __float2bfloat16(v.y);
    __nv_bfloat16 h2 = __float2bfloat16(v.z);
    __nv_bfloat16 h3 = __float2bfloat16(v.w);
    __nv_bfloat162 ph0; ph0.x = h0; ph0.y = h1;
    __nv_bfloat162 ph1; ph1.x = h2; ph1.y = h3;
    hi[2*i]   = ph0;
    hi[2*i+1] = ph1;
    __nv_bfloat162 pl0, pl1;
    pl0.x = __float2bfloat16(v.x - __bfloat162float(h0));
    pl0.y = __float2bfloat16(v.y - __bfloat162float(h1));
    pl1.x = __float2bfloat16(v.z - __bfloat162float(h2));
    pl1.y = __float2bfloat16(v.w - __bfloat162float(h3));
    lo[2*i]   = pl0;
    lo[2*i+1] = pl1;
}

// W: [K, N] row-major -> T{hi,lo}: [N, K] row-major (bf16 hi/lo split)
__global__ void transpose_split_kernel(const float* __restrict__ W,
                                       __nv_bfloat16* __restrict__ Thi,
                                       __nv_bfloat16* __restrict__ Tlo,
                                       int K, int N)
{
    __shared__ float t[32][33];
    int n0 = blockIdx.x * 32, k0 = blockIdx.y * 32;
    int tx = threadIdx.x, ty = threadIdx.y;   // (32, 8)
    #pragma unroll
    for (int j = 0; j < 32; j += 8)
        t[ty + j][tx] = W[(size_t)(k0 + ty + j) * N + n0 + tx];
    __syncthreads();
    #pragma unroll
    for (int j = 0; j < 32; j += 8) {
        float v = t[tx][ty + j];
        __nv_bfloat16 h = __float2bfloat16(v);
        __nv_bfloat16 l = __float2bfloat16(v - __bfloat162float(h));
        size_t oidx = (size_t)(n0 + ty + j) * K + k0 + tx;
        Thi[oidx] = h;
        Tlo[oidx] = l;
    }
}

// ======================= HMMA bf16-split GEMM ================================
// C[M,N] fp32 = A[M,K] @ B^T[N,K]; A,B as bf16 hi/lo pairs, K-major rows.
// Block tile 128x128x32; 8 warps in 2(M) x 4(N); per warp 64x32.
#define GBM 128
#define GBN 128
#define GBK 32
#define GEMM_THREADS 256
#define ROW_BYTES 80                          // 32 bf16 (64B) padded to 80B
#define ARR_BYTES (128 * ROW_BYTES)           // 10240
#define STAGE_BYTES (4 * ARR_BYTES)           // Ahi, Alo, Bhi, Blo = 40960
#define GEMM_SMEM (2 * STAGE_BYTES)           // 81920

__global__ void __launch_bounds__(GEMM_THREADS, 1)
gemm_mma_kernel(const __nv_bfloat16* __restrict__ Ahi, const __nv_bfloat16* __restrict__ Alo,
                const __nv_bfloat16* __restrict__ Bhi, const __nv_bfloat16* __restrict__ Blo,
                float* __restrict__ C, int M, int N, int K)
{
    extern __shared__ char smg[];
    const uint32_t sbase = smem_u32(smg);
    const int tid  = threadIdx.x;
    const int lane = tid & 31;
    const int wid  = tid >> 5;
    const int warp_m = wid >> 2;     // 0..1
    const int warp_n = wid & 3;      // 0..3
    const int m0 = blockIdx.y * GBM;
    const int n0 = blockIdx.x * GBN;

    const __nv_bfloat16* gsrc[4] = { Ahi, Alo, Bhi, Blo };

    // --- stage loader: 2048 16B-chunks, 8 per thread ---
    auto load_stage = [&](int kt) {
        const int buf = kt & 1;
        const uint32_t sdst0 = sbase + buf * STAGE_BYTES;
        const int kofs = kt * GBK;
        #pragma unroll
        for (int i = 0; i < 8; i++) {
            int t   = tid + GEMM_THREADS * i;   // 0..2047
            int arr = t >> 9;                   // 0..3
            int rem = t & 511;
            int row = rem >> 2;                 // 0..127
            int c   = rem & 3;                  // 0..3
            int grow = (arr < 2) ? (m0 + row) : (n0 + row);
            const __nv_bfloat16* gp = gsrc[arr] + (size_t)grow * K + kofs + c * 8;
            cp_async16(sdst0 + arr * ARR_BYTES + row * ROW_BYTES + c * 16, gp);
        }
    };

    float acc[4][4][4];
    #pragma unroll
    for (int i = 0; i < 4; i++)
        #pragma unroll
        for (int j = 0; j < 4; j++)
            #pragma unroll
            for (int r = 0; r < 4; r++) acc[i][j][r] = 0.f;

    const int ktiles = K / GBK;

    load_stage(0);
    CP_COMMIT();

    // precomputed fragment address pieces
    const uint32_t a_row_b = (uint32_t)(warp_m * 64 + (lane & 15)) * ROW_BYTES
                           + ((lane >> 4) * 16);
    const uint32_t b_row_b = (uint32_t)(warp_n * 32 + ((lane >> 4) & 1) * 8 + (lane & 7)) * ROW_BYTES
                           + (((lane >> 3) & 1) * 16);

    for (int kt = 0; kt < ktiles; kt++) {
        if (kt + 1 < ktiles) { load_stage(kt + 1); CP_COMMIT(); CP_WAIT1(); }
        else { CP_WAIT0(); }
        __syncthreads();

        const uint32_t st = sbase + (kt & 1) * STAGE_BYTES;
        #pragma unroll
        for (int s = 0; s < 2; s++) {          // two k16 steps
            const uint32_t koff = s * 32;
            uint32_t ah[4][4], al[4][4];
            #pragma unroll
            for (int mt = 0; mt < 4; mt++) {
                uint32_t ad = st + a_row_b + mt * (16 * ROW_BYTES) + koff;
                ldsm4(ah[mt], ad);                       // Ahi
                ldsm4(al[mt], ad + ARR_BYTES);           // Alo
            }
            uint32_t bh[2][4], bl[2][4];
            #pragma unroll
            for (int np = 0; np < 2; np++) {
                uint32_t bd = st + 2 * ARR_BYTES + b_row_b + np * (16 * ROW_BYTES) + koff;
                ldsm4(bh[np], bd);                       // Bhi
                ldsm4(bl[np], bd + ARR_BYTES);           // Blo
            }
            #pragma unroll
            for (int mt = 0; mt < 4; mt++)
                #pragma unroll
                for (int nt = 0; nt < 4; nt++) {
                    const uint32_t* bhp = &bh[nt >> 1][(nt & 1) * 2];
                    const uint32_t* blp = &bl[nt >> 1][(nt & 1) * 2];
                    mma_bf16(acc[mt][nt], ah[mt], bhp);
                    mma_bf16(acc[mt][nt], ah[mt], blp);
                    mma_bf16(acc[mt][nt], al[mt], bhp);
                }
        }
        __syncthreads();
    }

    // epilogue: direct fp32 stores
    #pragma unroll
    for (int mt = 0; mt < 4; mt++) {
        int r0 = m0 + warp_m * 64 + mt * 16 + (lane >> 2);
        #pragma unroll
        for (int nt = 0; nt < 4; nt++) {
            int cbase = n0 + warp_n * 32 + nt * 8 + (lane & 3) * 2;
            float2 v0 = make_float2(acc[mt][nt][0], acc[mt][nt][1]);
            float2 v1 = make_float2(acc[mt][nt][2], acc[mt][nt][3]);
            *(float2*)(C + (size_t)r0 * N + cbase)       = v0;
            *(float2*)(C + (size_t)(r0 + 8) * N + cbase) = v1;
        }
    }
}

// ---------------- RoPE (in-place) ------------------------------------------
__global__ void rope_kernel(float* __restrict__ buf, int n_heads, int total)
{
    int idx = blockIdx.x * blockDim.x + threadIdx.x;
    if (idx >= total) return;
    int j = idx & 63;
    int h = (idx >> 6) % n_heads;
    int r = idx / (64 * n_heads);
    int t = r & (TT - 1);

    float e = (float)(2 * j) * (1.0f / 128.0f);
    float inv = 1.0f / powf(10000.0f, e);
    float f = (float)t * inv;
    float c = cosf(f), s = sinf(f);

    float* p = buf + (size_t)r * (n_heads * DD) + h * DD;
    float x1 = p[j], x2 = p[j + 64];
    p[j]      = x1 * c - x2 * s;
    p[j + 64] = x2 * c + x1 * s;
}

// ---------------- Flash attention (causal, GQA) -----------------------------
#define BQ 32
#define BK 64
#define QS_STRIDE 132
#define KS_STRIDE 132
#define QS_OFF 0
#define KS_OFF (BQ * QS_STRIDE)
#define VS_OFF (KS_OFF + BK * KS_STRIDE)
#define P_OFF  (VS_OFF + BK * DD)
#define SMEM_FLOATS (P_OFF + BQ * BK)
#define SMEM_BYTES (SMEM_FLOATS * 4)
#define ATTN_SCALE 0.08838834764831843f

__global__ void __launch_bounds__(256) attn_kernel(
    const float* __restrict__ Q, const float* __restrict__ K,
    const float* __restrict__ V, float* __restrict__ O)
{
    extern __shared__ float sm[];
    float4* Qs4 = (float4*)(sm + QS_OFF);
    float4* Ks4 = (float4*)(sm + KS_OFF);
    float4* Vs4 = (float4*)(sm + VS_OFF);
    float*  Psm = sm + P_OFF;

    const int tid  = threadIdx.x;
    const int qloc = tid >> 3;
    const int g    = tid & 7;
    const int qi   = (gridDim.x - 1 - blockIdx.x);
    const int h    = blockIdx.y;
    const int b    = blockIdx.z;
    const int hk   = h >> 1;

    #pragma unroll
    for (int i = 0; i < 4; i++) {
        int lin = tid + 256 * i;
        int row = lin >> 5;
        int c4  = lin & 31;
        float4 qv = *(const float4*)(Q + ((size_t)(b * TT + qi * BQ + row) * HH + h) * DD + c4 * 4);
        Qs4[row * (QS_STRIDE / 4) + c4] = qv;
    }

    const int q_global = qi * BQ + qloc;
    float m = -INFINITY;
    float l = 0.f;
    float4 acc0 = {0,0,0,0}, acc1 = {0,0,0,0}, acc2 = {0,0,0,0}, acc3 = {0,0,0,0};

    const int ntiles = (qi * BQ + BQ - 1) / BK + 1;

    for (int t0 = 0; t0 < ntiles; t0++) {
        const int k0 = t0 * BK;
        __syncthreads();

        #pragma unroll
        for (int i = 0; i < 8; i++) {
            int lin = tid + 256 * i;
            int row = lin >> 5;
            int c4  = lin & 31;
            size_t gidx = ((size_t)(b * TT + k0 + row) * HKV + hk) * DD + c4 * 4;
            Ks4[row * (KS_STRIDE / 4) + c4] = *(const float4*)(K + gidx);
            Vs4[row * (DD / 4) + c4]        = *(const float4*)(V + gidx);
        }
        __syncthreads();

        float s8[8];
        #pragma unroll
        for (int j = 0; j < 8; j++) s8[j] = 0.f;

        #pragma unroll 4
        for (int d4 = 0; d4 < 32; d4++) {
            float4 qv = Qs4[qloc * (QS_STRIDE / 4) + d4];
            #pragma unroll
            for (int j = 0; j < 8; j++) {
                float4 kv = Ks4[(g + 8 * j) * (KS_STRIDE / 4) + d4];
                s8[j] += qv.x * kv.x + qv.y * kv.y + qv.z * kv.z + qv.w * kv.w;
            }
        }

        float mx = -INFINITY;
        #pragma unroll
        for (int j = 0; j < 8; j++) {
            int kg = k0 + g + 8 * j;
            float sv = s8[j] * ATTN_SCALE;
            if (kg > q_global) sv = -INFINITY;
            s8[j] = sv;
            mx = fmaxf(mx, sv);
        }
        #pragma unroll
        for (int off = 1; off < 8; off <<= 1)
            mx = fmaxf(mx, __shfl_xor_sync(0xffffffffu, mx, off));

        float m_new = fmaxf(m, mx);
        float alpha = expf(m - m_new);

        float lsum = 0.f;
        #pragma unroll
        for (int j = 0; j < 8; j++) {
            float p = expf(s8[j] - m_new);
            lsum += p;
            Psm[qloc * BK + g + 8 * j] = p;
        }
        #pragma unroll
        for (int off = 1; off < 8; off <<= 1)
            lsum += __shfl_xor_sync(0xffffffffu, lsum, off);

        l = l * alpha + lsum;
        m = m_new;
        acc0.x *= alpha; acc0.y *= alpha; acc0.z *= alpha; acc0.w *= alpha;
        acc1.x *= alpha; acc1.y *= alpha; acc1.z *= alpha; acc1.w *= alpha;
        acc2.x *= alpha; acc2.y *= alpha; acc2.z *= alpha; acc2.w *= alpha;
        acc3.x *= alpha; acc3.y *= alpha; acc3.z *= alpha; acc3.w *= alpha;

        __syncwarp();

        #pragma unroll 4
        for (int k = 0; k < BK; k++) {
            float p = Psm[qloc * BK + k];
            float4 v0 = Vs4[k * 32 + g];
            float4 v1 = Vs4[k * 32 + g + 8];
            float4 v2 = Vs4[k * 32 + g + 16];
            float4 v3 = Vs4[k * 32 + g + 24];
            acc0.x += p * v0.x; acc0.y += p * v0.y; acc0.z += p * v0.z; acc0.w += p * v0.w;
            acc1.x += p * v1.x; acc1.y += p * v1.y; acc1.z += p * v1.z; acc1.w += p * v1.w;
            acc2.x += p * v2.x; acc2.y += p * v2.y; acc2.z += p * v2.z; acc2.w += p * v2.w;
            acc3.x += p * v3.x; acc3.y += p * v3.y; acc3.z += p * v3.z; acc3.w += p * v3.w;
        }
    }

    float invl = 1.0f / l;
    float* orow = O + ((size_t)(b * TT) + q_global) * CC + h * DD;
    float4 w;
    w = make_float4(acc0.x*invl, acc0.y*invl, acc0.z*invl, acc0.w*invl); *(float4*)(orow + g*4)      = w;
    w = make_float4(acc1.x*invl, acc1.y*invl, acc1.z*invl, acc1.w*invl); *(float4*)(orow + g*4 + 32) = w;
    w = make_float4(acc2.x*invl, acc2.y*invl, acc2.z*invl, acc2.w*invl); *(float4*)(orow + g*4 + 64) = w;
    w = make_float4(acc3.x*invl, acc3.y*invl, acc3.z*invl, acc3.w*invl); *(float4*)(orow + g*4 + 96) = w;
}

// ---------------- host entry -------------------------------------------------
extern "C" void kernel_launch(void* const* d_in, const int* in_sizes, int n_in,
                              void* d_out, int out_size)
{
    const float* x  = (const float*)d_in[0];
    const float* Wq = (const float*)d_in[1];
    const float* Wk = (const float*)d_in[2];
    const float* Wv = (const float*)d_in[3];
    const float* Wp = (const float*)d_in[4];
    float* out = (float*)d_out;

    float *q, *k, *v, *o;
    cudaGetSymbolAddress((void**)&q, g_q);
    cudaGetSymbolAddress((void**)&k, g_k);
    cudaGetSymbolAddress((void**)&v, g_v);
    cudaGetSymbolAddress((void**)&o, g_o);

    __nv_bfloat16 *xhi, *xlo, *ohi, *olo, *wqh, *wql, *wkh, *wkl, *wvh, *wvl, *wph, *wpl;
    cudaGetSymbolAddress((void**)&xhi, g_xhi); cudaGetSymbolAddress((void**)&xlo, g_xlo);
    cudaGetSymbolAddress((void**)&ohi, g_ohi); cudaGetSymbolAddress((void**)&olo, g_olo);
    cudaGetSymbolAddress((void**)&wqh, g_wqh); cudaGetSymbolAddress((void**)&wql, g_wql);
    cudaGetSymbolAddress((void**)&wkh, g_wkh); cudaGetSymbolAddress((void**)&wkl, g_wkl);
    cudaGetSymbolAddress((void**)&wvh, g_wvh); cudaGetSymbolAddress((void**)&wvl, g_wvl);
    cudaGetSymbolAddress((void**)&wph, g_wph); cudaGetSymbolAddress((void**)&wpl, g_wpl);

    cudaFuncSetAttribute(gemm_mma_kernel, cudaFuncAttributeMaxDynamicSharedMemorySize, GEMM_SMEM);
    cudaFuncSetAttribute(attn_kernel, cudaFuncAttributeMaxDynamicSharedMemorySize, SMEM_BYTES);

    // split x into bf16 hi/lo
    {
        int n4 = (NROW * CC) / 4;
        split_kernel<<<(n4 + 255) / 256, 256>>>((const float4*)x,
            (__nv_bfloat162*)xhi, (__nv_bfloat162*)xlo, n4);
    }
    // transpose + split weights: W[K,N] -> Wt[N,K]
    transpose_split_kernel<<<dim3(CC/32, CC/32), dim3(32, 8)>>>(Wq, wqh, wql, CC, CC);
    transpose_split_kernel<<<dim3((HKV*DD)/32, CC/32), dim3(32, 8)>>>(Wk, wkh, wkl, CC, HKV*DD);
    transpose_split_kernel<<<dim3((HKV*DD)/32, CC/32), dim3(32, 8)>>>(Wv, wvh, wvl, CC, HKV*DD);
    transpose_split_kernel<<<dim3(CC/32, CC/32), dim3(32, 8)>>>(Wp, wph, wpl, CC, CC);

    // projections on tensor cores (HMMA)
    gemm_mma_kernel<<<dim3(CC/GBN, NROW/GBM), GEMM_THREADS, GEMM_SMEM>>>(xhi, xlo, wqh, wql, q, NROW, CC, CC);
    gemm_mma_kernel<<<dim3((HKV*DD)/GBN, NROW/GBM), GEMM_THREADS, GEMM_SMEM>>>(xhi, xlo, wkh, wkl, k, NROW, HKV*DD, CC);
    gemm_mma_kernel<<<dim3((HKV*DD)/GBN, NROW/GBM), GEMM_THREADS, GEMM_SMEM>>>(xhi, xlo, wvh, wvl, v, NROW, HKV*DD, CC);

    // RoPE
    {
        int totq = NROW * HH * 64;
        rope_kernel<<<(totq + 255) / 256, 256>>>(q, HH, totq);
        int totk = NROW * HKV * 64;
        rope_kernel<<<(totk + 255) / 256, 256>>>(k, HKV, totk);
    }

    // attention
    attn_kernel<<<dim3(TT / BQ, HH, BB), 256, SMEM_BYTES>>>(q, k, v, o);

    // split attention output, then output projection on tensor cores
    {
        int n4 = (NROW * CC) / 4;
        split_kernel<<<(n4 + 255) / 256, 256>>>((const float4*)o,
            (__nv_bfloat162*)ohi, (__nv_bfloat162*)olo, n4);
    }
    gemm_mma_kernel<<<dim3(CC/GBN, NROW/GBM), GEMM_THREADS, GEMM_SMEM>>>(ohi, olo, wph, wpl, out, NROW, CC, CC);
}

// round 4
// speedup vs baseline: 3.2985x; 2.2484x over previous
#include <cuda_runtime.h>
#include <cuda_bf16.h>
#include <math.h>
#include <cstdint>

// Problem constants
#define BB 2
#define TT 2048
#define CC 2048
#define HH 16
#define HKV 8
#define DD 128
#define NROW (BB*TT)          // 4096

// ---------------- scratch (device globals; no allocation allowed) ----------
__device__ float g_q[(size_t)NROW * CC];
__device__ float g_k[(size_t)NROW * (HKV*DD)];
__device__ float g_v[(size_t)NROW * (HKV*DD)];

__device__ __align__(16) __nv_bfloat16 g_xhi[(size_t)NROW * CC];
__device__ __align__(16) __nv_bfloat16 g_xlo[(size_t)NROW * CC];
__device__ __align__(16) __nv_bfloat16 g_ohi[(size_t)NROW * CC];
__device__ __align__(16) __nv_bfloat16 g_olo[(size_t)NROW * CC];
__device__ __align__(16) __nv_bfloat16 g_wqh[(size_t)CC * CC];
__device__ __align__(16) __nv_bfloat16 g_wql[(size_t)CC * CC];
__device__ __align__(16) __nv_bfloat16 g_wph[(size_t)CC * CC];
__device__ __align__(16) __nv_bfloat16 g_wpl[(size_t)CC * CC];
__device__ __align__(16) __nv_bfloat16 g_wkh[(size_t)(HKV*DD) * CC];
__device__ __align__(16) __nv_bfloat16 g_wkl[(size_t)(HKV*DD) * CC];
__device__ __align__(16) __nv_bfloat16 g_wvh[(size_t)(HKV*DD) * CC];
__device__ __align__(16) __nv_bfloat16 g_wvl[(size_t)(HKV*DD) * CC];

// ======================= low-level helpers ==================================
__device__ __forceinline__ uint32_t smem_u32(const void* p) {
    uint32_t a;
    asm("{ .reg .u64 t; cvta.to.shared.u64 t, %1; cvt.u32.u64 %0, t; }"
        : "=r"(a) : "l"(p));
    return a;
}
__device__ __forceinline__ void ldsm4(uint32_t* r, uint32_t addr) {
    asm volatile("ldmatrix.sync.aligned.m8n8.x4.shared.b16 {%0,%1,%2,%3}, [%4];"
        : "=r"(r[0]), "=r"(r[1]), "=r"(r[2]), "=r"(r[3]) : "r"(addr));
}
__device__ __forceinline__ void ldsm4t(uint32_t* r, uint32_t addr) {
    asm volatile("ldmatrix.sync.aligned.m8n8.x4.trans.shared.b16 {%0,%1,%2,%3}, [%4];"
        : "=r"(r[0]), "=r"(r[1]), "=r"(r[2]), "=r"(r[3]) : "r"(addr));
}
__device__ __forceinline__ void mma_bf16(float* d, const uint32_t* a, const uint32_t* b) {
    asm volatile(
        "mma.sync.aligned.m16n8k16.row.col.f32.bf16.bf16.f32 "
        "{%0,%1,%2,%3}, {%4,%5,%6,%7}, {%8,%9}, {%0,%1,%2,%3};"
        : "+f"(d[0]), "+f"(d[1]), "+f"(d[2]), "+f"(d[3])
        : "r"(a[0]), "r"(a[1]), "r"(a[2]), "r"(a[3]), "r"(b[0]), "r"(b[1]));
}
__device__ __forceinline__ void cp_async16(uint32_t dst, const void* src) {
    asm volatile("cp.async.cg.shared.global [%0], [%1], 16;\n" :: "r"(dst), "l"(src));
}
#define CP_COMMIT() asm volatile("cp.async.commit_group;\n" ::: "memory")
#define CP_WAIT1()  asm volatile("cp.async.wait_group 1;\n" ::: "memory")
#define CP_WAIT0()  asm volatile("cp.async.wait_group 0;\n" ::: "memory")

__device__ __forceinline__ __nv_bfloat162 bfpair(float a, float b) {
    __nv_bfloat162 r; r.x = __float2bfloat16(a); r.y = __float2bfloat16(b); return r;
}
__device__ __forceinline__ void packsplit(float a, float b, uint32_t& hi, uint32_t& lo) {
    __nv_bfloat16 ha = __float2bfloat16(a), hb = __float2bfloat16(b);
    __nv_bfloat162 H; H.x = ha; H.y = hb;
    __nv_bfloat162 L;
    L.x = __float2bfloat16(a - __bfloat162float(ha));
    L.y = __float2bfloat16(b - __bfloat162float(hb));
    hi = *(uint32_t*)&H; lo = *(uint32_t*)&L;
}

// ======================= conversion kernels =================================
__global__ void split_kernel(const float4* __restrict__ in,
                             __nv_bfloat162* __restrict__ hi,
                             __nv_bfloat162* __restrict__ lo, int n4)
{
    int i = blockIdx.x * blockDim.x + threadIdx.x;
    if (i >= n4) return;
    float4 v = in[i];
    __nv_bfloat16 h0 = __float2bfloat16(v.x);
    __nv_bfloat16 h1 = __float2bfloat16(v.y);
    __nv_bfloat16 h2 = __float2bfloat16(v.z);
    __nv_bfloat16 h3 = __float2bfloat16(v.w);
    __nv_bfloat162 ph0; ph0.x = h0; ph0.y = h1;
    __nv_bfloat162 ph1; ph1.x = h2; ph1.y = h3;
    hi[2*i]   = ph0;
    hi[2*i+1] = ph1;
    __nv_bfloat162 pl0, pl1;
    pl0.x = __float2bfloat16(v.x - __bfloat162float(h0));
    pl0.y = __float2bfloat16(v.y - __bfloat162float(h1));
    pl1.x = __float2bfloat16(v.z - __bfloat162float(h2));
    pl1.y = __float2bfloat16(v.w - __bfloat162float(h3));
    lo[2*i]   = pl0;
    lo[2*i+1] = pl1;
}

// W: [K, N] row-major -> T{hi,lo}: [N, K] row-major (bf16 hi/lo split)
__global__ void transpose_split_kernel(const float* __restrict__ W,
                                       __nv_bfloat16* __restrict__ Thi,
                                       __nv_bfloat16* __restrict__ Tlo,
                                       int K, int N)
{
    __shared__ float t[32][33];
    int n0 = blockIdx.x * 32, k0 = blockIdx.y * 32;
    int tx = threadIdx.x, ty = threadIdx.y;   // (32, 8)
    #pragma unroll
    for (int j = 0; j < 32; j += 8)
        t[ty + j][tx] = W[(size_t)(k0 + ty + j) * N + n0 + tx];
    __syncthreads();
    #pragma unroll
    for (int j = 0; j < 32; j += 8) {
        float v = t[tx][ty + j];
        __nv_bfloat16 h = __float2bfloat16(v);
        __nv_bfloat16 l = __float2bfloat16(v - __bfloat162float(h));
        size_t oidx = (size_t)(n0 + ty + j) * K + k0 + tx;
        Thi[oidx] = h;
        Tlo[oidx] = l;
    }
}

// ======================= HMMA bf16-split GEMM ================================
#define GBM 128
#define GBN 128
#define GBK 32
#define GEMM_THREADS 256
#define ROW_BYTES 80
#define ARR_BYTES (128 * ROW_BYTES)
#define STAGE_BYTES (4 * ARR_BYTES)
#define GEMM_SMEM (2 * STAGE_BYTES)

__global__ void __launch_bounds__(GEMM_THREADS, 1)
gemm_mma_kernel(const __nv_bfloat16* __restrict__ Ahi, const __nv_bfloat16* __restrict__ Alo,
                const __nv_bfloat16* __restrict__ Bhi, const __nv_bfloat16* __restrict__ Blo,
                float* __restrict__ C, int M, int N, int K)
{
    extern __shared__ char smg[];
    const uint32_t sbase = smem_u32(smg);
    const int tid  = threadIdx.x;
    const int lane = tid & 31;
    const int wid  = tid >> 5;
    const int warp_m = wid >> 2;
    const int warp_n = wid & 3;
    const int m0 = blockIdx.y * GBM;
    const int n0 = blockIdx.x * GBN;

    const __nv_bfloat16* gsrc[4] = { Ahi, Alo, Bhi, Blo };

    auto load_stage = [&](int kt) {
        const int buf = kt & 1;
        const uint32_t sdst0 = sbase + buf * STAGE_BYTES;
        const int kofs = kt * GBK;
        #pragma unroll
        for (int i = 0; i < 8; i++) {
            int t   = tid + GEMM_THREADS * i;
            int arr = t >> 9;
            int rem = t & 511;
            int row = rem >> 2;
            int c   = rem & 3;
            int grow = (arr < 2) ? (m0 + row) : (n0 + row);
            const __nv_bfloat16* gp = gsrc[arr] + (size_t)grow * K + kofs + c * 8;
            cp_async16(sdst0 + arr * ARR_BYTES + row * ROW_BYTES + c * 16, gp);
        }
    };

    float acc[4][4][4];
    #pragma unroll
    for (int i = 0; i < 4; i++)
        #pragma unroll
        for (int j = 0; j < 4; j++)
            #pragma unroll
            for (int r = 0; r < 4; r++) acc[i][j][r] = 0.f;

    const int ktiles = K / GBK;

    load_stage(0);
    CP_COMMIT();

    const uint32_t a_row_b = (uint32_t)(warp_m * 64 + (lane & 15)) * ROW_BYTES
                           + ((lane >> 4) * 16);
    const uint32_t b_row_b = (uint32_t)(warp_n * 32 + ((lane >> 4) & 1) * 8 + (lane & 7)) * ROW_BYTES
                           + (((lane >> 3) & 1) * 16);

    for (int kt = 0; kt < ktiles; kt++) {
        if (kt + 1 < ktiles) { load_stage(kt + 1); CP_COMMIT(); CP_WAIT1(); }
        else { CP_WAIT0(); }
        __syncthreads();

        const uint32_t st = sbase + (kt & 1) * STAGE_BYTES;
        #pragma unroll
        for (int s = 0; s < 2; s++) {
            const uint32_t koff = s * 32;
            uint32_t ah[4][4], al[4][4];
            #pragma unroll
            for (int mt = 0; mt < 4; mt++) {
                uint32_t ad = st + a_row_b + mt * (16 * ROW_BYTES) + koff;
                ldsm4(ah[mt], ad);
                ldsm4(al[mt], ad + ARR_BYTES);
            }
            uint32_t bh[2][4], bl[2][4];
            #pragma unroll
            for (int np = 0; np < 2; np++) {
                uint32_t bd = st + 2 * ARR_BYTES + b_row_b + np * (16 * ROW_BYTES) + koff;
                ldsm4(bh[np], bd);
                ldsm4(bl[np], bd + ARR_BYTES);
            }
            #pragma unroll
            for (int mt = 0; mt < 4; mt++)
                #pragma unroll
                for (int nt = 0; nt < 4; nt++) {
                    const uint32_t* bhp = &bh[nt >> 1][(nt & 1) * 2];
                    const uint32_t* blp = &bl[nt >> 1][(nt & 1) * 2];
                    mma_bf16(acc[mt][nt], ah[mt], bhp);
                    mma_bf16(acc[mt][nt], ah[mt], blp);
                    mma_bf16(acc[mt][nt], al[mt], bhp);
                }
        }
        __syncthreads();
    }

    #pragma unroll
    for (int mt = 0; mt < 4; mt++) {
        int r0 = m0 + warp_m * 64 + mt * 16 + (lane >> 2);
        #pragma unroll
        for (int nt = 0; nt < 4; nt++) {
            int cbase = n0 + warp_n * 32 + nt * 8 + (lane & 3) * 2;
            float2 v0 = make_float2(acc[mt][nt][0], acc[mt][nt][1]);
            float2 v1 = make_float2(acc[mt][nt][2], acc[mt][nt][3]);
            *(float2*)(C + (size_t)r0 * N + cbase)       = v0;
            *(float2*)(C + (size_t)(r0 + 8) * N + cbase) = v1;
        }
    }
}

// ---------------- RoPE (in-place) ------------------------------------------
__global__ void rope_kernel(float* __restrict__ buf, int n_heads, int total)
{
    int idx = blockIdx.x * blockDim.x + threadIdx.x;
    if (idx >= total) return;
    int j = idx & 63;
    int h = (idx >> 6) % n_heads;
    int r = idx / (64 * n_heads);
    int t = r & (TT - 1);

    float e = (float)(2 * j) * (1.0f / 128.0f);
    float inv = 1.0f / powf(10000.0f, e);
    float f = (float)t * inv;
    float c = cosf(f), s = sinf(f);

    float* p = buf + (size_t)r * (n_heads * DD) + h * DD;
    float x1 = p[j], x2 = p[j + 64];
    p[j]      = x1 * c - x2 * s;
    p[j + 64] = x2 * c + x1 * s;
}

// ================= Flash attention on HMMA (bf16 hi/lo split) ================
// Grid: (T/ABQ, H, B); 256 threads (8 warps x 16 Q rows).
#define ABQ 128
#define ABK 64
#define AROW 136                       // bf16 elements per padded row (272B)
#define AQH 0
#define AQL (ABQ*AROW)                 // 17408
#define AKH (2*ABQ*AROW)               // 34816
#define AKL (AKH + ABK*AROW)           // 43520
#define AVH (AKL + ABK*AROW)           // 52224
#define AVL (AVH + ABK*AROW)           // 60928
#define ASM_ELEMS (AVL + ABK*AROW)     // 69632
#define ASM_BYTES (ASM_ELEMS*2)        // 139264
#define ATTN_SCALE 0.08838834764831843f

__global__ void __launch_bounds__(256, 1)
attn_mma_kernel(const float* __restrict__ Q, const float* __restrict__ K,
                const float* __restrict__ V,
                __nv_bfloat16* __restrict__ Ohi, __nv_bfloat16* __restrict__ Olo)
{
    extern __shared__ __align__(1024) char smA[];
    __nv_bfloat16* sm = (__nv_bfloat16*)smA;
    const uint32_t sb = smem_u32(smA);

    const int tid  = threadIdx.x;
    const int lane = tid & 31;
    const int w    = tid >> 5;
    const int qi   = gridDim.x - 1 - blockIdx.x;   // big tiles first
    const int h    = blockIdx.y;
    const int b    = blockIdx.z;
    const int hk   = h >> 1;
    const int qbase = qi * ABQ;

    // ---- load + split Q tile (128 x 128 fp32 -> bf16 hi/lo smem) ----
    #pragma unroll
    for (int i = 0; i < 16; i++) {
        int task = tid + 256 * i;         // 0..4095
        int row = task >> 5;
        int c4  = task & 31;
        float4 v = *(const float4*)(Q + ((size_t)(b*TT + qbase + row)*HH + h)*DD + c4*4);
        int off = row * AROW + c4 * 4;
        __nv_bfloat16 h0 = __float2bfloat16(v.x), h1 = __float2bfloat16(v.y);
        __nv_bfloat16 h2 = __float2bfloat16(v.z), h3 = __float2bfloat16(v.w);
        __nv_bfloat162 p0; p0.x = h0; p0.y = h1;
        __nv_bfloat162 p1; p1.x = h2; p1.y = h3;
        *(__nv_bfloat162*)(sm + AQH + off)     = p0;
        *(__nv_bfloat162*)(sm + AQH + off + 2) = p1;
        *(__nv_bfloat162*)(sm + AQL + off)     = bfpair(v.x - __bfloat162float(h0),
                                                        v.y - __bfloat162float(h1));
        *(__nv_bfloat162*)(sm + AQL + off + 2) = bfpair(v.z - __bfloat162float(h2),
                                                        v.w - __bfloat162float(h3));
    }

    float m0 = -INFINITY, m1 = -INFINITY, l0 = 0.f, l1 = 0.f;
    float oacc[16][4];
    #pragma unroll
    for (int j = 0; j < 16; j++)
        #pragma unroll
        for (int r = 0; r < 4; r++) oacc[j][r] = 0.f;

    // fragment address pieces
    const uint32_t qA_h = sb + 2*(uint32_t)(AQH + (w*16 + (lane & 15))*AROW) + (lane >> 4)*16;
    const uint32_t qA_l = qA_h + 2*(uint32_t)(AQL - AQH);
    const int krow  = ((lane >> 4) & 1)*8 + (lane & 7);
    const int kcolh = ((lane >> 3) & 1)*16;
    const int vrow  = ((lane >> 3) & 1)*8 + (lane & 7);
    const int vcolh = (lane >> 4)*16;

    const int ntiles = 2*qi + 2;
    const int qr0 = qbase + w*16 + (lane >> 2);

    for (int t = 0; t < ntiles; t++) {
        const int k0 = t * ABK;
        __syncthreads();   // prev tile's smem reads done

        // ---- load + split K,V tile (64 x 128 each) ----
        #pragma unroll
        for (int i = 0; i < 8; i++) {
            int task = tid + 256 * i;     // 0..2047
            int row = task >> 5;
            int c4  = task & 31;
            size_t gb = ((size_t)(b*TT + k0 + row)*HKV + hk)*DD + c4*4;
            float4 kv = *(const float4*)(K + gb);
            float4 vv = *(const float4*)(V + gb);
            int off = row * AROW + c4 * 4;
            __nv_bfloat16 kh0 = __float2bfloat16(kv.x), kh1 = __float2bfloat16(kv.y);
            __nv_bfloat16 kh2 = __float2bfloat16(kv.z), kh3 = __float2bfloat16(kv.w);
            __nv_bfloat162 kp0; kp0.x = kh0; kp0.y = kh1;
            __nv_bfloat162 kp1; kp1.x = kh2; kp1.y = kh3;
            *(__nv_bfloat162*)(sm + AKH + off)     = kp0;
            *(__nv_bfloat162*)(sm + AKH + off + 2) = kp1;
            *(__nv_bfloat162*)(sm + AKL + off)     = bfpair(kv.x - __bfloat162float(kh0),
                                                            kv.y - __bfloat162float(kh1));
            *(__nv_bfloat162*)(sm + AKL + off + 2) = bfpair(kv.z - __bfloat162float(kh2),
                                                            kv.w - __bfloat162float(kh3));
            __nv_bfloat16 vh0 = __float2bfloat16(vv.x), vh1 = __float2bfloat16(vv.y);
            __nv_bfloat16 vh2 = __float2bfloat16(vv.z), vh3 = __float2bfloat16(vv.w);
            __nv_bfloat162 vp0; vp0.x = vh0; vp0.y = vh1;
            __nv_bfloat162 vp1; vp1.x = vh2; vp1.y = vh3;
            *(__nv_bfloat162*)(sm + AVH + off)     = vp0;
            *(__nv_bfloat162*)(sm + AVH + off + 2) = vp1;
            *(__nv_bfloat162*)(sm + AVL + off)     = bfpair(vv.x - __bfloat162float(vh0),
                                                            vv.y - __bfloat162float(vh1));
            *(__nv_bfloat162*)(sm + AVL + off + 2) = bfpair(vv.z - __bfloat162float(vh2),
                                                            vv.w - __bfloat162float(vh3));
        }
        __syncthreads();

        // ---- S = Q K^T (3 split passes) ----
        float sacc[8][4];
        #pragma unroll
        for (int j = 0; j < 8; j++)
            #pragma unroll
            for (int r = 0; r < 4; r++) sacc[j][r] = 0.f;

        #pragma unroll
        for (int s = 0; s < 8; s++) {
            uint32_t ah[4], al[4];
            ldsm4(ah, qA_h + s*32);
            ldsm4(al, qA_l + s*32);
            #pragma unroll
            for (int jj = 0; jj < 4; jj++) {
                uint32_t kh[4], kl[4];
                uint32_t ka = sb + 2*(uint32_t)(AKH + (16*jj + krow)*AROW) + s*32 + kcolh;
                ldsm4(kh, ka);
                ldsm4(kl, ka + 2*(uint32_t)(AKL - AKH));
                mma_bf16(sacc[2*jj],   ah, &kh[0]);
                mma_bf16(sacc[2*jj],   ah, &kl[0]);
                mma_bf16(sacc[2*jj],   al, &kh[0]);
                mma_bf16(sacc[2*jj+1], ah, &kh[2]);
                mma_bf16(sacc[2*jj+1], ah, &kl[2]);
                mma_bf16(sacc[2*jj+1], al, &kh[2]);
            }
        }

        // ---- online softmax ----
        const bool domask = (t >= ntiles - 2);
        float mx0 = -INFINITY, mx1 = -INFINITY;
        #pragma unroll
        for (int j = 0; j < 8; j++) {
            #pragma unroll
            for (int r = 0; r < 4; r++) {
                float sv = sacc[j][r] * ATTN_SCALE;
                if (domask) {
                    int col = k0 + 8*j + (lane & 3)*2 + (r & 1);
                    int qr  = qr0 + ((r >= 2) ? 8 : 0);
                    if (col > qr) sv = -INFINITY;
                }
                sacc[j][r] = sv;
                if (r < 2) mx0 = fmaxf(mx0, sv); else mx1 = fmaxf(mx1, sv);
            }
        }
        mx0 = fmaxf(mx0, __shfl_xor_sync(0xffffffffu, mx0, 1));
        mx0 = fmaxf(mx0, __shfl_xor_sync(0xffffffffu, mx0, 2));
        mx1 = fmaxf(mx1, __shfl_xor_sync(0xffffffffu, mx1, 1));
        mx1 = fmaxf(mx1, __shfl_xor_sync(0xffffffffu, mx1, 2));

        float m0n = fmaxf(m0, mx0), m1n = fmaxf(m1, mx1);
        float a0 = __expf(m0 - m0n), a1 = __expf(m1 - m1n);
        float ls0 = 0.f, ls1 = 0.f;
        #pragma unroll
        for (int j = 0; j < 8; j++) {
            float p0 = __expf(sacc[j][0] - m0n);
            float p1 = __expf(sacc[j][1] - m0n);
            float p2 = __expf(sacc[j][2] - m1n);
            float p3 = __expf(sacc[j][3] - m1n);
            sacc[j][0] = p0; sacc[j][1] = p1; sacc[j][2] = p2; sacc[j][3] = p3;
            ls0 += p0 + p1; ls1 += p2 + p3;
        }
        ls0 += __shfl_xor_sync(0xffffffffu, ls0, 1);
        ls0 += __shfl_xor_sync(0xffffffffu, ls0, 2);
        ls1 += __shfl_xor_sync(0xffffffffu, ls1, 1);
        ls1 += __shfl_xor_sync(0xffffffffu, ls1, 2);

        l0 = l0 * a0 + ls0;
        l1 = l1 * a1 + ls1;
        m0 = m0n; m1 = m1n;
        #pragma unroll
        for (int j = 0; j < 16; j++) {
            oacc[j][0] *= a0; oacc[j][1] *= a0;
            oacc[j][2] *= a1; oacc[j][3] *= a1;
        }

        // ---- O += P V (3 split passes, P from registers) ----
        #pragma unroll
        for (int s2 = 0; s2 < 4; s2++) {
            uint32_t ahp[4], alp[4];
            packsplit(sacc[2*s2][0],   sacc[2*s2][1],   ahp[0], alp[0]);
            packsplit(sacc[2*s2][2],   sacc[2*s2][3],   ahp[1], alp[1]);
            packsplit(sacc[2*s2+1][0], sacc[2*s2+1][1], ahp[2], alp[2]);
            packsplit(sacc[2*s2+1][2], sacc[2*s2+1][3], ahp[3], alp[3]);
            uint32_t va = sb + 2*(uint32_t)(AVH + (16*s2 + vrow)*AROW) + vcolh;
            #pragma unroll
            for (int dd = 0; dd < 8; dd++) {
                uint32_t vh[4], vl[4];
                ldsm4t(vh, va + dd*32);
                ldsm4t(vl, va + dd*32 + 2*(uint32_t)(AVL - AVH));
                mma_bf16(oacc[2*dd],   ahp, &vh[0]);
                mma_bf16(oacc[2*dd],   ahp, &vl[0]);
                mma_bf16(oacc[2*dd],   alp, &vh[0]);
                mma_bf16(oacc[2*dd+1], ahp, &vh[2]);
                mma_bf16(oacc[2*dd+1], ahp, &vl[2]);
                mma_bf16(oacc[2*dd+1], alp, &vh[2]);
            }
        }
    }

    // ---- epilogue: normalize + write bf16 hi/lo directly ----
    float i0 = 1.f / l0, i1 = 1.f / l1;
    const int row0 = qbase + w*16 + (lane >> 2);
    const int col0 = (lane & 3)*2;
    #pragma unroll
    for (int j = 0; j < 16; j++) {
        int col = j*8 + col0;
        size_t base0 = ((size_t)(b*TT + row0)*HH + h)*DD + col;
        size_t base1 = base0 + (size_t)8*HH*DD;
        uint32_t hp, lp;
        packsplit(oacc[j][0]*i0, oacc[j][1]*i0, hp, lp);
        *(uint32_t*)(Ohi + base0) = hp;
        *(uint32_t*)(Olo + base0) = lp;
        packsplit(oacc[j][2]*i1, oacc[j][3]*i1, hp, lp);
        *(uint32_t*)(Ohi + base1) = hp;
        *(uint32_t*)(Olo + base1) = lp;
    }
}

// ---------------- host entry -------------------------------------------------
extern "C" void kernel_launch(void* const* d_in, const int* in_sizes, int n_in,
                              void* d_out, int out_size)
{
    const float* x  = (const float*)d_in[0];
    const float* Wq = (const float*)d_in[1];
    const float* Wk = (const float*)d_in[2];
    const float* Wv = (const float*)d_in[3];
    const float* Wp = (const float*)d_in[4];
    float* out = (float*)d_out;

    float *q, *k, *v;
    cudaGetSymbolAddress((void**)&q, g_q);
    cudaGetSymbolAddress((void**)&k, g_k);
    cudaGetSymbolAddress((void**)&v, g_v);

    __nv_bfloat16 *xhi, *xlo, *ohi, *olo, *wqh, *wql, *wkh, *wkl, *wvh, *wvl, *wph, *wpl;
    cudaGetSymbolAddress((void**)&xhi, g_xhi); cudaGetSymbolAddress((void**)&xlo, g_xlo);
    cudaGetSymbolAddress((void**)&ohi, g_ohi); cudaGetSymbolAddress((void**)&olo, g_olo);
    cudaGetSymbolAddress((void**)&wqh, g_wqh); cudaGetSymbolAddress((void**)&wql, g_wql);
    cudaGetSymbolAddress((void**)&wkh, g_wkh); cudaGetSymbolAddress((void**)&wkl, g_wkl);
    cudaGetSymbolAddress((void**)&wvh, g_wvh); cudaGetSymbolAddress((void**)&wvl, g_wvl);
    cudaGetSymbolAddress((void**)&wph, g_wph); cudaGetSymbolAddress((void**)&wpl, g_wpl);

    cudaFuncSetAttribute(gemm_mma_kernel, cudaFuncAttributeMaxDynamicSharedMemorySize, GEMM_SMEM);
    cudaFuncSetAttribute(attn_mma_kernel, cudaFuncAttributeMaxDynamicSharedMemorySize, ASM_BYTES);

    // split x into bf16 hi/lo
    {
        int n4 = (NROW * CC) / 4;
        split_kernel<<<(n4 + 255) / 256, 256>>>((const float4*)x,
            (__nv_bfloat162*)xhi, (__nv_bfloat162*)xlo, n4);
    }
    // transpose + split weights: W[K,N] -> Wt[N,K]
    transpose_split_kernel<<<dim3(CC/32, CC/32), dim3(32, 8)>>>(Wq, wqh, wql, CC, CC);
    transpose_split_kernel<<<dim3((HKV*DD)/32, CC/32), dim3(32, 8)>>>(Wk, wkh, wkl, CC, HKV*DD);
    transpose_split_kernel<<<dim3((HKV*DD)/32, CC/32), dim3(32, 8)>>>(Wv, wvh, wvl, CC, HKV*DD);
    transpose_split_kernel<<<dim3(CC/32, CC/32), dim3(32, 8)>>>(Wp, wph, wpl, CC, CC);

    // projections on tensor cores (HMMA)
    gemm_mma_kernel<<<dim3(CC/GBN, NROW/GBM), GEMM_THREADS, GEMM_SMEM>>>(xhi, xlo, wqh, wql, q, NROW, CC, CC);
    gemm_mma_kernel<<<dim3((HKV*DD)/GBN, NROW/GBM), GEMM_THREADS, GEMM_SMEM>>>(xhi, xlo, wkh, wkl, k, NROW, HKV*DD, CC);
    gemm_mma_kernel<<<dim3((HKV*DD)/GBN, NROW/GBM), GEMM_THREADS, GEMM_SMEM>>>(xhi, xlo, wvh, wvl, v, NROW, HKV*DD, CC);

    // RoPE
    {
        int totq = NROW * HH * 64;
        rope_kernel<<<(totq + 255) / 256, 256>>>(q, HH, totq);
        int totk = NROW * HKV * 64;
        rope_kernel<<<(totk + 255) / 256, 256>>>(k, HKV, totk);
    }

    // attention on tensor cores; writes bf16 hi/lo O directly
    attn_mma_kernel<<<dim3(TT / ABQ, HH, BB), 256, ASM_BYTES>>>(q, k, v, ohi, olo);

    // output projection on tensor cores
    gemm_mma_kernel<<<dim3(CC/GBN, NROW/GBM), GEMM_THREADS, GEMM_SMEM>>>(ohi, olo, wph, wpl, out, NROW, CC, CC);
}

// round 5
// speedup vs baseline: 3.3603x; 1.0187x over previous
#include <cuda_runtime.h>
#include <cuda_bf16.h>
#include <math.h>
#include <cstdint>

// Problem constants
#define BB 2
#define TT 2048
#define CC 2048
#define HH 16
#define HKV 8
#define DD 128
#define NROW (BB*TT)          // 4096

// ---------------- scratch (device globals; no allocation allowed) ----------
__device__ float g_q[(size_t)NROW * CC];
__device__ float g_k[(size_t)NROW * (HKV*DD)];
__device__ float g_v[(size_t)NROW * (HKV*DD)];

__device__ __align__(16) __nv_bfloat16 g_xhi[(size_t)NROW * CC];
__device__ __align__(16) __nv_bfloat16 g_xlo[(size_t)NROW * CC];
__device__ __align__(16) __nv_bfloat16 g_ohi[(size_t)NROW * CC];
__device__ __align__(16) __nv_bfloat16 g_olo[(size_t)NROW * CC];
__device__ __align__(16) __nv_bfloat16 g_wqh[(size_t)CC * CC];
__device__ __align__(16) __nv_bfloat16 g_wql[(size_t)CC * CC];
__device__ __align__(16) __nv_bfloat16 g_wph[(size_t)CC * CC];
__device__ __align__(16) __nv_bfloat16 g_wpl[(size_t)CC * CC];
__device__ __align__(16) __nv_bfloat16 g_wkh[(size_t)(HKV*DD) * CC];
__device__ __align__(16) __nv_bfloat16 g_wkl[(size_t)(HKV*DD) * CC];
__device__ __align__(16) __nv_bfloat16 g_wvh[(size_t)(HKV*DD) * CC];
__device__ __align__(16) __nv_bfloat16 g_wvl[(size_t)(HKV*DD) * CC];

// head-major bf16 hi/lo Q/K/V for attention
__device__ __align__(16) __nv_bfloat16 g_qh[(size_t)BB * HH * TT * DD];
__device__ __align__(16) __nv_bfloat16 g_ql[(size_t)BB * HH * TT * DD];
__device__ __align__(16) __nv_bfloat16 g_kh[(size_t)BB * HKV * TT * DD];
__device__ __align__(16) __nv_bfloat16 g_kl[(size_t)BB * HKV * TT * DD];
__device__ __align__(16) __nv_bfloat16 g_vh[(size_t)BB * HKV * TT * DD];
__device__ __align__(16) __nv_bfloat16 g_vl[(size_t)BB * HKV * TT * DD];

// ======================= low-level helpers ==================================
__device__ __forceinline__ uint32_t smem_u32(const void* p) {
    uint32_t a;
    asm("{ .reg .u64 t; cvta.to.shared.u64 t, %1; cvt.u32.u64 %0, t; }"
        : "=r"(a) : "l"(p));
    return a;
}
__device__ __forceinline__ void ldsm4(uint32_t* r, uint32_t addr) {
    asm volatile("ldmatrix.sync.aligned.m8n8.x4.shared.b16 {%0,%1,%2,%3}, [%4];"
        : "=r"(r[0]), "=r"(r[1]), "=r"(r[2]), "=r"(r[3]) : "r"(addr));
}
__device__ __forceinline__ void ldsm4t(uint32_t* r, uint32_t addr) {
    asm volatile("ldmatrix.sync.aligned.m8n8.x4.trans.shared.b16 {%0,%1,%2,%3}, [%4];"
        : "=r"(r[0]), "=r"(r[1]), "=r"(r[2]), "=r"(r[3]) : "r"(addr));
}
__device__ __forceinline__ void mma_bf16(float* d, const uint32_t* a, const uint32_t* b) {
    asm volatile(
        "mma.sync.aligned.m16n8k16.row.col.f32.bf16.bf16.f32 "
        "{%0,%1,%2,%3}, {%4,%5,%6,%7}, {%8,%9}, {%0,%1,%2,%3};"
        : "+f"(d[0]), "+f"(d[1]), "+f"(d[2]), "+f"(d[3])
        : "r"(a[0]), "r"(a[1]), "r"(a[2]), "r"(a[3]), "r"(b[0]), "r"(b[1]));
}
__device__ __forceinline__ void cp_async16(uint32_t dst, const void* src) {
    asm volatile("cp.async.cg.shared.global [%0], [%1], 16;\n" :: "r"(dst), "l"(src));
}
#define CP_COMMIT() asm volatile("cp.async.commit_group;\n" ::: "memory")
#define CP_WAIT1()  asm volatile("cp.async.wait_group 1;\n" ::: "memory")
#define CP_WAIT0()  asm volatile("cp.async.wait_group 0;\n" ::: "memory")

__device__ __forceinline__ __nv_bfloat162 bfpair(float a, float b) {
    __nv_bfloat162 r; r.x = __float2bfloat16(a); r.y = __float2bfloat16(b); return r;
}
__device__ __forceinline__ void packsplit(float a, float b, uint32_t& hi, uint32_t& lo) {
    __nv_bfloat16 ha = __float2bfloat16(a), hb = __float2bfloat16(b);
    __nv_bfloat162 H; H.x = ha; H.y = hb;
    __nv_bfloat162 L;
    L.x = __float2bfloat16(a - __bfloat162float(ha));
    L.y = __float2bfloat16(b - __bfloat162float(hb));
    hi = *(uint32_t*)&H; lo = *(uint32_t*)&L;
}

// ======================= conversion kernels =================================
__global__ void split_kernel(const float4* __restrict__ in,
                             __nv_bfloat162* __restrict__ hi,
                             __nv_bfloat162* __restrict__ lo, int n4)
{
    int i = blockIdx.x * blockDim.x + threadIdx.x;
    if (i >= n4) return;
    float4 v = in[i];
    __nv_bfloat16 h0 = __float2bfloat16(v.x);
    __nv_bfloat16 h1 = __float2bfloat16(v.y);
    __nv_bfloat16 h2 = __float2bfloat16(v.z);
    __nv_bfloat16 h3 = __float2bfloat16(v.w);
    __nv_bfloat162 ph0; ph0.x = h0; ph0.y = h1;
    __nv_bfloat162 ph1; ph1.x = h2; ph1.y = h3;
    hi[2*i]   = ph0;
    hi[2*i+1] = ph1;
    __nv_bfloat162 pl0, pl1;
    pl0.x = __float2bfloat16(v.x - __bfloat162float(h0));
    pl0.y = __float2bfloat16(v.y - __bfloat162float(h1));
    pl1.x = __float2bfloat16(v.z - __bfloat162float(h2));
    pl1.y = __float2bfloat16(v.w - __bfloat162float(h3));
    lo[2*i]   = pl0;
    lo[2*i+1] = pl1;
}

// W: [K, N] row-major -> T{hi,lo}: [N, K] row-major (bf16 hi/lo split)
__global__ void transpose_split_kernel(const float* __restrict__ W,
                                       __nv_bfloat16* __restrict__ Thi,
                                       __nv_bfloat16* __restrict__ Tlo,
                                       int K, int N)
{
    __shared__ float t[32][33];
    int n0 = blockIdx.x * 32, k0 = blockIdx.y * 32;
    int tx = threadIdx.x, ty = threadIdx.y;   // (32, 8)
    #pragma unroll
    for (int j = 0; j < 32; j += 8)
        t[ty + j][tx] = W[(size_t)(k0 + ty + j) * N + n0 + tx];
    __syncthreads();
    #pragma unroll
    for (int j = 0; j < 32; j += 8) {
        float v = t[tx][ty + j];
        __nv_bfloat16 h = __float2bfloat16(v);
        __nv_bfloat16 l = __float2bfloat16(v - __bfloat162float(h));
        size_t oidx = (size_t)(n0 + ty + j) * K + k0 + tx;
        Thi[oidx] = h;
        Tlo[oidx] = l;
    }
}

// RoPE + bf16 hi/lo split + relayout [b,t,h,d] -> [b,h,t,d]
__global__ void rope_split_kernel(const float* __restrict__ in,
                                  __nv_bfloat16* __restrict__ oh,
                                  __nv_bfloat16* __restrict__ ol,
                                  int n_heads, int total)
{
    int idx = blockIdx.x * blockDim.x + threadIdx.x;
    if (idx >= total) return;
    int j = idx & 63;
    int h = (idx >> 6) % n_heads;
    int r = idx / (64 * n_heads);
    int b = r >> 11;
    int t = r & (TT - 1);

    float e = (float)(2 * j) * (1.0f / 128.0f);
    float inv = 1.0f / powf(10000.0f, e);
    float f = (float)t * inv;
    float c = cosf(f), s = sinf(f);

    const float* p = in + (size_t)r * (n_heads * DD) + h * DD;
    float x1 = p[j], x2 = p[j + 64];
    float y1 = x1 * c - x2 * s;
    float y2 = x2 * c + x1 * s;

    size_t ob = ((size_t)(b * n_heads + h) * TT + t) * DD + j;
    __nv_bfloat16 h1 = __float2bfloat16(y1);
    __nv_bfloat16 h2 = __float2bfloat16(y2);
    oh[ob]      = h1;
    oh[ob + 64] = h2;
    ol[ob]      = __float2bfloat16(y1 - __bfloat162float(h1));
    ol[ob + 64] = __float2bfloat16(y2 - __bfloat162float(h2));
}

// V: bf16 hi/lo split + relayout [b,t,hk,d] -> [b,hk,t,d]
__global__ void v_split_kernel(const float* __restrict__ in,
                               __nv_bfloat16* __restrict__ oh,
                               __nv_bfloat16* __restrict__ ol, int total4)
{
    int idx = blockIdx.x * blockDim.x + threadIdx.x;
    if (idx >= total4) return;
    int c4 = idx & 31;
    int h  = (idx >> 5) & 7;
    int r  = idx >> 8;
    int b  = r >> 11;
    int t  = r & (TT - 1);
    float4 v = *(const float4*)(in + (size_t)r * (HKV*DD) + h * DD + c4 * 4);
    size_t ob = ((size_t)(b * HKV + h) * TT + t) * DD + c4 * 4;
    __nv_bfloat16 h0 = __float2bfloat16(v.x), h1 = __float2bfloat16(v.y);
    __nv_bfloat16 h2 = __float2bfloat16(v.z), h3 = __float2bfloat16(v.w);
    __nv_bfloat162 p0; p0.x = h0; p0.y = h1;
    __nv_bfloat162 p1; p1.x = h2; p1.y = h3;
    *(__nv_bfloat162*)(oh + ob)     = p0;
    *(__nv_bfloat162*)(oh + ob + 2) = p1;
    *(__nv_bfloat162*)(ol + ob)     = bfpair(v.x - __bfloat162float(h0),
                                             v.y - __bfloat162float(h1));
    *(__nv_bfloat162*)(ol + ob + 2) = bfpair(v.z - __bfloat162float(h2),
                                             v.w - __bfloat162float(h3));
}

// ======================= HMMA bf16-split GEMM ================================
#define GBM 128
#define GBN 128
#define GBK 32
#define GEMM_THREADS 256
#define ROW_BYTES 80
#define ARR_BYTES (128 * ROW_BYTES)
#define STAGE_BYTES (4 * ARR_BYTES)
#define GEMM_SMEM (2 * STAGE_BYTES)

__global__ void __launch_bounds__(GEMM_THREADS, 1)
gemm_mma_kernel(const __nv_bfloat16* __restrict__ Ahi, const __nv_bfloat16* __restrict__ Alo,
                const __nv_bfloat16* __restrict__ Bhi, const __nv_bfloat16* __restrict__ Blo,
                float* __restrict__ C, int M, int N, int K)
{
    extern __shared__ char smg[];
    const uint32_t sbase = smem_u32(smg);
    const int tid  = threadIdx.x;
    const int lane = tid & 31;
    const int wid  = tid >> 5;
    const int warp_m = wid >> 2;
    const int warp_n = wid & 3;
    const int m0 = blockIdx.y * GBM;
    const int n0 = blockIdx.x * GBN;

    const __nv_bfloat16* gsrc[4] = { Ahi, Alo, Bhi, Blo };

    auto load_stage = [&](int kt) {
        const int buf = kt & 1;
        const uint32_t sdst0 = sbase + buf * STAGE_BYTES;
        const int kofs = kt * GBK;
        #pragma unroll
        for (int i = 0; i < 8; i++) {
            int t   = tid + GEMM_THREADS * i;
            int arr = t >> 9;
            int rem = t & 511;
            int row = rem >> 2;
            int c   = rem & 3;
            int grow = (arr < 2) ? (m0 + row) : (n0 + row);
            const __nv_bfloat16* gp = gsrc[arr] + (size_t)grow * K + kofs + c * 8;
            cp_async16(sdst0 + arr * ARR_BYTES + row * ROW_BYTES + c * 16, gp);
        }
    };

    float acc[4][4][4];
    #pragma unroll
    for (int i = 0; i < 4; i++)
        #pragma unroll
        for (int j = 0; j < 4; j++)
            #pragma unroll
            for (int r = 0; r < 4; r++) acc[i][j][r] = 0.f;

    const int ktiles = K / GBK;

    load_stage(0);
    CP_COMMIT();

    const uint32_t a_row_b = (uint32_t)(warp_m * 64 + (lane & 15)) * ROW_BYTES
                           + ((lane >> 4) * 16);
    const uint32_t b_row_b = (uint32_t)(warp_n * 32 + ((lane >> 4) & 1) * 8 + (lane & 7)) * ROW_BYTES
                           + (((lane >> 3) & 1) * 16);

    for (int kt = 0; kt < ktiles; kt++) {
        if (kt + 1 < ktiles) { load_stage(kt + 1); CP_COMMIT(); CP_WAIT1(); }
        else { CP_WAIT0(); }
        __syncthreads();

        const uint32_t st = sbase + (kt & 1) * STAGE_BYTES;
        #pragma unroll
        for (int s = 0; s < 2; s++) {
            const uint32_t koff = s * 32;
            uint32_t ah[4][4], al[4][4];
            #pragma unroll
            for (int mt = 0; mt < 4; mt++) {
                uint32_t ad = st + a_row_b + mt * (16 * ROW_BYTES) + koff;
                ldsm4(ah[mt], ad);
                ldsm4(al[mt], ad + ARR_BYTES);
            }
            uint32_t bh[2][4], bl[2][4];
            #pragma unroll
            for (int np = 0; np < 2; np++) {
                uint32_t bd = st + 2 * ARR_BYTES + b_row_b + np * (16 * ROW_BYTES) + koff;
                ldsm4(bh[np], bd);
                ldsm4(bl[np], bd + ARR_BYTES);
            }
            #pragma unroll
            for (int mt = 0; mt < 4; mt++)
                #pragma unroll
                for (int nt = 0; nt < 4; nt++) {
                    const uint32_t* bhp = &bh[nt >> 1][(nt & 1) * 2];
                    const uint32_t* blp = &bl[nt >> 1][(nt & 1) * 2];
                    mma_bf16(acc[mt][nt], ah[mt], bhp);
                    mma_bf16(acc[mt][nt], ah[mt], blp);
                    mma_bf16(acc[mt][nt], al[mt], bhp);
                }
        }
        __syncthreads();
    }

    #pragma unroll
    for (int mt = 0; mt < 4; mt++) {
        int r0 = m0 + warp_m * 64 + mt * 16 + (lane >> 2);
        #pragma unroll
        for (int nt = 0; nt < 4; nt++) {
            int cbase = n0 + warp_n * 32 + nt * 8 + (lane & 3) * 2;
            float2 v0 = make_float2(acc[mt][nt][0], acc[mt][nt][1]);
            float2 v1 = make_float2(acc[mt][nt][2], acc[mt][nt][3]);
            *(float2*)(C + (size_t)r0 * N + cbase)       = v0;
            *(float2*)(C + (size_t)(r0 + 8) * N + cbase) = v1;
        }
    }
}

// ================= Flash attention on HMMA (bf16 hi/lo, cp.async) ===========
#define ABQ 128
#define ABK 64
#define AROW 136                       // bf16 elements per padded row (272B)
#define AQH 0
#define AQL (ABQ*AROW)
#define AKH (2*ABQ*AROW)
#define AKL (AKH + ABK*AROW)
#define AVH (AKL + ABK*AROW)
#define AVL (AVH + ABK*AROW)
#define ASM_ELEMS (AVL + ABK*AROW)
#define ASM_BYTES (ASM_ELEMS*2)        // 139264
#define ATTN_SCALE 0.08838834764831843f

__global__ void __launch_bounds__(256, 1)
attn_mma_kernel(const __nv_bfloat16* __restrict__ Qh, const __nv_bfloat16* __restrict__ Ql,
                const __nv_bfloat16* __restrict__ Kh, const __nv_bfloat16* __restrict__ Kl,
                const __nv_bfloat16* __restrict__ Vh, const __nv_bfloat16* __restrict__ Vl,
                __nv_bfloat16* __restrict__ Ohi, __nv_bfloat16* __restrict__ Olo)
{
    extern __shared__ __align__(1024) char smA[];
    const uint32_t sb = smem_u32(smA);

    const int tid  = threadIdx.x;
    const int lane = tid & 31;
    const int w    = tid >> 5;
    const int qi   = gridDim.x - 1 - blockIdx.x;   // big tiles first
    const int h    = blockIdx.y;
    const int b    = blockIdx.z;
    const int hk   = h >> 1;
    const int qbase = qi * ABQ;

    const size_t qb0 = ((size_t)(b * HH + h) * TT + qbase) * DD;
    const size_t kb0 = ((size_t)(b * HKV + hk) * TT) * DD;
    const __nv_bfloat16* kvsrc[4] = { Kh, Kl, Vh, Vl };

    // ---- Q tile: cp.async bf16 hi/lo (group 0) ----
    #pragma unroll
    for (int i = 0; i < 16; i++) {
        int task = tid + 256 * i;        // 0..4095
        int arr = task >> 11;            // 0 hi, 1 lo
        int rem = task & 2047;
        int row = rem >> 4;
        int c   = rem & 15;
        const __nv_bfloat16* src = (arr ? Ql : Qh) + qb0 + (size_t)row * DD + c * 8;
        cp_async16(sb + 2 * (uint32_t)((arr ? AQL : AQH) + row * AROW) + c * 16, src);
    }
    CP_COMMIT();

    float m0 = -INFINITY, m1 = -INFINITY, l0 = 0.f, l1 = 0.f;
    float oacc[16][4];
    #pragma unroll
    for (int j = 0; j < 16; j++)
        #pragma unroll
        for (int r = 0; r < 4; r++) oacc[j][r] = 0.f;

    const uint32_t qA_h = sb + 2*(uint32_t)(AQH + (w*16 + (lane & 15))*AROW) + (lane >> 4)*16;
    const uint32_t qA_l = qA_h + 2*(uint32_t)(AQL - AQH);
    const int krow  = ((lane >> 4) & 1)*8 + (lane & 7);
    const int kcolh = ((lane >> 3) & 1)*16;
    const int vrow  = ((lane >> 3) & 1)*8 + (lane & 7);
    const int vcolh = (lane >> 4)*16;

    const int ntiles = 2*qi + 2;
    const int qr0 = qbase + w*16 + (lane >> 2);

    for (int t = 0; t < ntiles; t++) {
        const int k0 = t * ABK;
        __syncthreads();   // prev tile's smem reads done before overwrite

        // ---- K tile (group), then V tile (group) ----
        #pragma unroll
        for (int i = 0; i < 8; i++) {
            int task = tid + 256 * i;    // 0..2047 : arr 0,1 (Kh,Kl)
            int arr = task >> 10;
            int rem = task & 1023;
            int row = rem >> 4;
            int c   = rem & 15;
            cp_async16(sb + 2*(uint32_t)(AKH + arr*(ABK*AROW) + row*AROW) + c*16,
                       kvsrc[arr] + kb0 + (size_t)(k0 + row)*DD + c*8);
        }
        CP_COMMIT();
        #pragma unroll
        for (int i = 8; i < 16; i++) {
            int task = tid + 256 * i;    // 2048..4095 : arr 2,3 (Vh,Vl)
            int arr = task >> 10;
            int rem = task & 1023;
            int row = rem >> 4;
            int c   = rem & 15;
            cp_async16(sb + 2*(uint32_t)(AKH + arr*(ABK*AROW) + row*AROW) + c*16,
                       kvsrc[arr] + kb0 + (size_t)(k0 + row)*DD + c*8);
        }
        CP_COMMIT();

        CP_WAIT1();          // Q + K complete (V may still be in flight)
        __syncthreads();

        // ---- S = Q K^T (3 split passes) ----
        float sacc[8][4];
        #pragma unroll
        for (int j = 0; j < 8; j++)
            #pragma unroll
            for (int r = 0; r < 4; r++) sacc[j][r] = 0.f;

        #pragma unroll
        for (int s = 0; s < 8; s++) {
            uint32_t ah[4], al[4];
            ldsm4(ah, qA_h + s*32);
            ldsm4(al, qA_l + s*32);
            #pragma unroll
            for (int jj = 0; jj < 4; jj++) {
                uint32_t kh[4], kl[4];
                uint32_t ka = sb + 2*(uint32_t)(AKH + (16*jj + krow)*AROW) + s*32 + kcolh;
                ldsm4(kh, ka);
                ldsm4(kl, ka + 2*(uint32_t)(AKL - AKH));
                mma_bf16(sacc[2*jj],   ah, &kh[0]);
                mma_bf16(sacc[2*jj],   ah, &kl[0]);
                mma_bf16(sacc[2*jj],   al, &kh[0]);
                mma_bf16(sacc[2*jj+1], ah, &kh[2]);
                mma_bf16(sacc[2*jj+1], ah, &kl[2]);
                mma_bf16(sacc[2*jj+1], al, &kh[2]);
            }
        }

        CP_WAIT0();          // V tile complete
        __syncthreads();

        // ---- online softmax ----
        const bool domask = (t >= ntiles - 2);
        float mx0 = -INFINITY, mx1 = -INFINITY;
        #pragma unroll
        for (int j = 0; j < 8; j++) {
            #pragma unroll
            for (int r = 0; r < 4; r++) {
                float sv = sacc[j][r] * ATTN_SCALE;
                if (domask) {
                    int col = k0 + 8*j + (lane & 3)*2 + (r & 1);
                    int qr  = qr0 + ((r >= 2) ? 8 : 0);
                    if (col > qr) sv = -INFINITY;
                }
                sacc[j][r] = sv;
                if (r < 2) mx0 = fmaxf(mx0, sv); else mx1 = fmaxf(mx1, sv);
            }
        }
        mx0 = fmaxf(mx0, __shfl_xor_sync(0xffffffffu, mx0, 1));
        mx0 = fmaxf(mx0, __shfl_xor_sync(0xffffffffu, mx0, 2));
        mx1 = fmaxf(mx1, __shfl_xor_sync(0xffffffffu, mx1, 1));
        mx1 = fmaxf(mx1, __shfl_xor_sync(0xffffffffu, mx1, 2));

        float m0n = fmaxf(m0, mx0), m1n = fmaxf(m1, mx1);
        float a0 = __expf(m0 - m0n), a1 = __expf(m1 - m1n);
        float ls0 = 0.f, ls1 = 0.f;
        #pragma unroll
        for (int j = 0; j < 8; j++) {
            float p0 = __expf(sacc[j][0] - m0n);
            float p1 = __expf(sacc[j][1] - m0n);
            float p2 = __expf(sacc[j][2] - m1n);
            float p3 = __expf(sacc[j][3] - m1n);
            sacc[j][0] = p0; sacc[j][1] = p1; sacc[j][2] = p2; sacc[j][3] = p3;
            ls0 += p0 + p1; ls1 += p2 + p3;
        }
        ls0 += __shfl_xor_sync(0xffffffffu, ls0, 1);
        ls0 += __shfl_xor_sync(0xffffffffu, ls0, 2);
        ls1 += __shfl_xor_sync(0xffffffffu, ls1, 1);
        ls1 += __shfl_xor_sync(0xffffffffu, ls1, 2);

        l0 = l0 * a0 + ls0;
        l1 = l1 * a1 + ls1;
        m0 = m0n; m1 = m1n;
        #pragma unroll
        for (int j = 0; j < 16; j++) {
            oacc[j][0] *= a0; oacc[j][1] *= a0;
            oacc[j][2] *= a1; oacc[j][3] *= a1;
        }

        // ---- O += P V (3 split passes, P from registers) ----
        #pragma unroll
        for (int s2 = 0; s2 < 4; s2++) {
            uint32_t ahp[4], alp[4];
            packsplit(sacc[2*s2][0],   sacc[2*s2][1],   ahp[0], alp[0]);
            packsplit(sacc[2*s2][2],   sacc[2*s2][3],   ahp[1], alp[1]);
            packsplit(sacc[2*s2+1][0], sacc[2*s2+1][1], ahp[2], alp[2]);
            packsplit(sacc[2*s2+1][2], sacc[2*s2+1][3], ahp[3], alp[3]);
            uint32_t va = sb + 2*(uint32_t)(AVH + (16*s2 + vrow)*AROW) + vcolh;
            #pragma unroll
            for (int dd = 0; dd < 8; dd++) {
                uint32_t vh[4], vl[4];
                ldsm4t(vh, va + dd*32);
                ldsm4t(vl, va + dd*32 + 2*(uint32_t)(AVL - AVH));
                mma_bf16(oacc[2*dd],   ahp, &vh[0]);
                mma_bf16(oacc[2*dd],   ahp, &vl[0]);
                mma_bf16(oacc[2*dd],   alp, &vh[0]);
                mma_bf16(oacc[2*dd+1], ahp, &vh[2]);
                mma_bf16(oacc[2*dd+1], ahp, &vl[2]);
                mma_bf16(oacc[2*dd+1], alp, &vh[2]);
            }
        }
    }

    // ---- epilogue: normalize + write bf16 hi/lo ([b,t,h*d] for Wp GEMM) ----
    float i0 = 1.f / l0, i1 = 1.f / l1;
    const int row0 = qbase + w*16 + (lane >> 2);
    const int col0 = (lane & 3)*2;
    #pragma unroll
    for (int j = 0; j < 16; j++) {
        int col = j*8 + col0;
        size_t base0 = ((size_t)(b*TT + row0)*HH + h)*DD + col;
        size_t base1 = base0 + (size_t)8*HH*DD;
        uint32_t hp, lp;
        packsplit(oacc[j][0]*i0, oacc[j][1]*i0, hp, lp);
        *(uint32_t*)(Ohi + base0) = hp;
        *(uint32_t*)(Olo + base0) = lp;
        packsplit(oacc[j][2]*i1, oacc[j][3]*i1, hp, lp);
        *(uint32_t*)(Ohi + base1) = hp;
        *(uint32_t*)(Olo + base1) = lp;
    }
}

// ---------------- host entry -------------------------------------------------
extern "C" void kernel_launch(void* const* d_in, const int* in_sizes, int n_in,
                              void* d_out, int out_size)
{
    const float* x  = (const float*)d_in[0];
    const float* Wq = (const float*)d_in[1];
    const float* Wk = (const float*)d_in[2];
    const float* Wv = (const float*)d_in[3];
    const float* Wp = (const float*)d_in[4];
    float* out = (float*)d_out;

    float *q, *k, *v;
    cudaGetSymbolAddress((void**)&q, g_q);
    cudaGetSymbolAddress((void**)&k, g_k);
    cudaGetSymbolAddress((void**)&v, g_v);

    __nv_bfloat16 *xhi, *xlo, *ohi, *olo, *wqh, *wql, *wkh, *wkl, *wvh, *wvl, *wph, *wpl;
    __nv_bfloat16 *qh, *ql, *kh, *kl, *vh, *vl;
    cudaGetSymbolAddress((void**)&xhi, g_xhi); cudaGetSymbolAddress((void**)&xlo, g_xlo);
    cudaGetSymbolAddress((void**)&ohi, g_ohi); cudaGetSymbolAddress((void**)&olo, g_olo);
    cudaGetSymbolAddress((void**)&wqh, g_wqh); cudaGetSymbolAddress((void**)&wql, g_wql);
    cudaGetSymbolAddress((void**)&wkh, g_wkh); cudaGetSymbolAddress((void**)&wkl, g_wkl);
    cudaGetSymbolAddress((void**)&wvh, g_wvh); cudaGetSymbolAddress((void**)&wvl, g_wvl);
    cudaGetSymbolAddress((void**)&wph, g_wph); cudaGetSymbolAddress((void**)&wpl, g_wpl);
    cudaGetSymbolAddress((void**)&qh, g_qh);   cudaGetSymbolAddress((void**)&ql, g_ql);
    cudaGetSymbolAddress((void**)&kh, g_kh);   cudaGetSymbolAddress((void**)&kl, g_kl);
    cudaGetSymbolAddress((void**)&vh, g_vh);   cudaGetSymbolAddress((void**)&vl, g_vl);

    cudaFuncSetAttribute(gemm_mma_kernel, cudaFuncAttributeMaxDynamicSharedMemorySize, GEMM_SMEM);
    cudaFuncSetAttribute(attn_mma_kernel, cudaFuncAttributeMaxDynamicSharedMemorySize, ASM_BYTES);

    // split x into bf16 hi/lo
    {
        int n4 = (NROW * CC) / 4;
        split_kernel<<<(n4 + 255) / 256, 256>>>((const float4*)x,
            (__nv_bfloat162*)xhi, (__nv_bfloat162*)xlo, n4);
    }
    // transpose + split weights: W[K,N] -> Wt[N,K]
    transpose_split_kernel<<<dim3(CC/32, CC/32), dim3(32, 8)>>>(Wq, wqh, wql, CC, CC);
    transpose_split_kernel<<<dim3((HKV*DD)/32, CC/32), dim3(32, 8)>>>(Wk, wkh, wkl, CC, HKV*DD);
    transpose_split_kernel<<<dim3((HKV*DD)/32, CC/32), dim3(32, 8)>>>(Wv, wvh, wvl, CC, HKV*DD);
    transpose_split_kernel<<<dim3(CC/32, CC/32), dim3(32, 8)>>>(Wp, wph, wpl, CC, CC);

    // projections on tensor cores (HMMA), fp32 outputs
    gemm_mma_kernel<<<dim3(CC/GBN, NROW/GBM), GEMM_THREADS, GEMM_SMEM>>>(xhi, xlo, wqh, wql, q, NROW, CC, CC);
    gemm_mma_kernel<<<dim3((HKV*DD)/GBN, NROW/GBM), GEMM_THREADS, GEMM_SMEM>>>(xhi, xlo, wkh, wkl, k, NROW, HKV*DD, CC);
    gemm_mma_kernel<<<dim3((HKV*DD)/GBN, NROW/GBM), GEMM_THREADS, GEMM_SMEM>>>(xhi, xlo, wvh, wvl, v, NROW, HKV*DD, CC);

    // RoPE + split + head-major relayout
    {
        int totq = NROW * HH * 64;
        rope_split_kernel<<<(totq + 255) / 256, 256>>>(q, qh, ql, HH, totq);
        int totk = NROW * HKV * 64;
        rope_split_kernel<<<(totk + 255) / 256, 256>>>(k, kh, kl, HKV, totk);
        int totv = NROW * HKV * 32;
        v_split_kernel<<<(totv + 255) / 256, 256>>>(v, vh, vl, totv);
    }

    // attention on tensor cores (bf16 in, bf16 hi/lo out)
    attn_mma_kernel<<<dim3(TT / ABQ, HH, BB), 256, ASM_BYTES>>>(qh, ql, kh, kl, vh, vl, ohi, olo);

    // output projection on tensor cores
    gemm_mma_kernel<<<dim3(CC/GBN, NROW/GBM), GEMM_THREADS, GEMM_SMEM>>>(ohi, olo, wph, wpl, out, NROW, CC, CC);
}